// round 1
// baseline (speedup 1.0000x reference)
#include <cuda_runtime.h>
#include <math.h>

#define B_  32
#define M_  64
#define K_  36
#define DS_ 512
#define DX_ 128
#define DQ_ 512
#define H_  256

#define ROWS_S (B_*M_)   // 2048
#define ROWS_X (B_*K_)   // 1152

// Scratch (allocation-free rule: __device__ globals)
__device__ __align__(16) float g_preq[B_*H_];          // 32*256
__device__ __align__(16) float g_C[ROWS_S*512];         // [2048,512]: cols 0:256 = pre_s, 256:512 = h1=relu(s2@h_w1+b)
__device__ __align__(16) float g_hs[ROWS_S*DX_];        // 2048*128
__device__ __align__(16) float g_base[ROWS_X*H_];       // 1152*256

// ---------------------------------------------------------------------------
// pre_q[b,h] = sum_d q[b,d] * w_q[d,h]   (w_q = score_w1 rows 640..1151)
// ---------------------------------------------------------------------------
__global__ void __launch_bounds__(256) preq_k(const float* __restrict__ q,
                                              const float* __restrict__ w1,
                                              float* __restrict__ preq)
{
    const int b = blockIdx.x;
    const int h = threadIdx.x;
    __shared__ float qs[DQ_];
    for (int d = threadIdx.x; d < DQ_; d += 256) qs[d] = q[b*DQ_ + d];
    __syncthreads();
    const float* wq = w1 + (size_t)(DS_ + DX_) * H_;
    float a0 = 0.f, a1 = 0.f, a2 = 0.f, a3 = 0.f;
    #pragma unroll 4
    for (int d = 0; d < DQ_; d += 4) {
        a0 = fmaf(qs[d+0], wq[(size_t)(d+0)*H_ + h], a0);
        a1 = fmaf(qs[d+1], wq[(size_t)(d+1)*H_ + h], a1);
        a2 = fmaf(qs[d+2], wq[(size_t)(d+2)*H_ + h], a2);
        a3 = fmaf(qs[d+3], wq[(size_t)(d+3)*H_ + h], a3);
    }
    preq[b*H_ + h] = (a0 + a1) + (a2 + a3);
}

// ---------------------------------------------------------------------------
// Tiled SGEMM: 64x64 tile, BK=16, 256 threads, 4x4 per-thread microtile.
// MODE 4: combined launch, N=512. n<256: C = A@B0 (plain).
//                                 n>=256: C = relu(A@B1 + bias1[n-256]).
// MODE 2: C = A@B0 + bias0[n]
// MODE 3: C = A@B0 + bias0[n] + aux[(row/36)*256 + n]
// All dims are exact multiples of the tiling (no bounds checks needed).
// ---------------------------------------------------------------------------
template<int MODE>
__global__ void __launch_bounds__(256) sgemm_k(
    const float* __restrict__ A, int lda,
    const float* __restrict__ B0, const float* __restrict__ B1, int ldb,
    float* __restrict__ Cc, int ldc,
    int Kdim,
    const float* __restrict__ bias0, const float* __restrict__ bias1,
    const float* __restrict__ aux)
{
    __shared__ float As[16][68];   // padded: 68*4B=272B row stride, 16B-aligned
    __shared__ float Bs[16][64];

    const int tid = threadIdx.x;
    const int tx = tid & 15;       // n direction
    const int ty = tid >> 4;       // m direction
    const int m0  = blockIdx.y * 64;
    const int n0g = blockIdx.x * 64;

    const float* Bp = B0;
    int ncol = n0g;
    const float* biasp = bias0;
    bool do_relu = false;
    if (MODE == 4) {
        if (n0g < 256) { Bp = B0; ncol = n0g; biasp = nullptr; }
        else           { Bp = B1; ncol = n0g - 256; biasp = bias1; do_relu = true; }
    }

    float acc[4][4] = {};

    const int la_m = tid >> 2;            // 0..63
    const int la_k = (tid & 3) << 2;      // 0,4,8,12
    const int lb_k = tid >> 4;            // 0..15
    const int lb_n = (tid & 15) << 2;     // 0..60

    for (int k0 = 0; k0 < Kdim; k0 += 16) {
        float4 av = *reinterpret_cast<const float4*>(&A[(size_t)(m0 + la_m) * lda + k0 + la_k]);
        float4 bv = *reinterpret_cast<const float4*>(&Bp[(size_t)(k0 + lb_k) * ldb + ncol + lb_n]);
        As[la_k + 0][la_m] = av.x;
        As[la_k + 1][la_m] = av.y;
        As[la_k + 2][la_m] = av.z;
        As[la_k + 3][la_m] = av.w;
        *reinterpret_cast<float4*>(&Bs[lb_k][lb_n]) = bv;
        __syncthreads();
        #pragma unroll
        for (int kk = 0; kk < 16; kk++) {
            float4 a = *reinterpret_cast<const float4*>(&As[kk][ty * 4]);
            float4 b = *reinterpret_cast<const float4*>(&Bs[kk][tx * 4]);
            float ar[4] = {a.x, a.y, a.z, a.w};
            float br[4] = {b.x, b.y, b.z, b.w};
            #pragma unroll
            for (int i = 0; i < 4; i++)
                #pragma unroll
                for (int j = 0; j < 4; j++)
                    acc[i][j] = fmaf(ar[i], br[j], acc[i][j]);
        }
        __syncthreads();
    }

    #pragma unroll
    for (int i = 0; i < 4; i++) {
        const int row = m0 + ty * 4 + i;
        float4 v;
        float* vp = &v.x;
        #pragma unroll
        for (int j = 0; j < 4; j++) {
            float val = acc[i][j];
            const int n = tx * 4 + j;
            if (MODE == 4) {
                if (do_relu) val = fmaxf(val + biasp[ncol + n], 0.f);
            } else if (MODE == 2) {
                val += biasp[ncol + n];
            } else if (MODE == 3) {
                val += biasp[ncol + n] + aux[(row / K_) * H_ + (ncol + n)];
            }
            vp[j] = val;
        }
        *reinterpret_cast<float4*>(&Cc[(size_t)row * ldc + n0g + tx * 4]) = v;
    }
}

// ---------------------------------------------------------------------------
// Fused: logits (relu-dot over H), softmax over m, agg over h_s, output write.
// One block per (b,k). 256 threads.
// ---------------------------------------------------------------------------
__global__ void __launch_bounds__(256) att_k(
    const float* __restrict__ Cmat,   // [2048,512], pre_s in cols 0..255
    const float* __restrict__ base,   // [1152,256]
    const float* __restrict__ hs,     // [2048,128]
    const float* __restrict__ w2,     // [256]
    const float* __restrict__ b2p,    // [1]
    const float* __restrict__ x0,     // [1152,128]
    float* __restrict__ out)          // [1152,256]
{
    const int bk = blockIdx.x;        // 0..1151
    const int b  = bk / K_;
    const int tid = threadIdx.x;

    __shared__ float base_s[H_];
    __shared__ float w2s[H_];
    __shared__ float logit[M_];
    __shared__ float ew[M_];
    __shared__ float s_mx, s_inv;

    base_s[tid] = base[(size_t)bk * H_ + tid];
    w2s[tid]    = w2[tid];
    __syncthreads();

    const int warp = tid >> 5, lane = tid & 31;
    const float b2 = b2p[0];
    const float* pres = Cmat + (size_t)(b * M_) * 512;

    #pragma unroll
    for (int mi = 0; mi < 8; mi++) {
        const int m = warp * 8 + mi;
        const float* row = pres + (size_t)m * 512;
        float acc = 0.f;
        #pragma unroll
        for (int j = 0; j < 8; j++) {
            const int h = lane + j * 32;
            const float v = row[h] + base_s[h];
            acc = fmaf(fmaxf(v, 0.f), w2s[h], acc);
        }
        #pragma unroll
        for (int off = 16; off; off >>= 1)
            acc += __shfl_xor_sync(0xffffffffu, acc, off);
        if (lane == 0) logit[m] = acc + b2;
    }
    __syncthreads();

    if (tid == 0) {
        float mx = -3.0e38f;
        for (int m = 0; m < M_; m++) mx = fmaxf(mx, logit[m]);
        s_mx = mx;
    }
    __syncthreads();
    if (tid < M_) ew[tid] = expf(logit[tid] - s_mx);
    __syncthreads();
    if (tid == 0) {
        float s = 0.f;
        for (int m = 0; m < M_; m++) s += ew[m];
        s_inv = 1.f / s;
    }
    __syncthreads();

    if (tid < 128) {
        const float* hb = hs + (size_t)(b * M_) * DX_ + tid;
        float acc = 0.f;
        #pragma unroll 8
        for (int m = 0; m < M_; m++)
            acc = fmaf(ew[m], hb[(size_t)m * DX_], acc);
        out[(size_t)bk * 256 + 128 + tid] = acc * s_inv;
    } else {
        const int f = tid - 128;
        out[(size_t)bk * 256 + f] = x0[(size_t)bk * DX_ + f];
    }
}

// ---------------------------------------------------------------------------
extern "C" void kernel_launch(void* const* d_in, const int* in_sizes, int n_in,
                              void* d_out, int out_size)
{
    (void)in_sizes; (void)n_in; (void)out_size;
    const float* s2  = (const float*)d_in[0];   // (32,64,512)
    const float* x0  = (const float*)d_in[1];   // (32,36,128)
    const float* q   = (const float*)d_in[2];   // (32,512)
    const float* w1  = (const float*)d_in[3];   // (1152,256)
    const float* b1  = (const float*)d_in[4];   // (256,)
    const float* w2  = (const float*)d_in[5];   // (256,1)
    const float* b2  = (const float*)d_in[6];   // (1,)
    const float* hw1 = (const float*)d_in[7];   // (512,256)
    const float* hb1 = (const float*)d_in[8];   // (256,)
    const float* hw2 = (const float*)d_in[9];   // (256,128)
    const float* hb2 = (const float*)d_in[10];  // (128,)
    float* out = (float*)d_out;

    float *preq, *C, *hs, *base;
    cudaGetSymbolAddress((void**)&preq, g_preq);
    cudaGetSymbolAddress((void**)&C,    g_C);
    cudaGetSymbolAddress((void**)&hs,   g_hs);
    cudaGetSymbolAddress((void**)&base, g_base);

    // 1) pre_q = q @ w_q
    preq_k<<<B_, 256>>>(q, w1, preq);

    // 2) C = [ s2 @ w_s | relu(s2 @ h_w1 + h_b1) ]   (2048 x 512, K=512)
    {
        dim3 grid(512 / 64, ROWS_S / 64);   // 8 x 32 = 256 blocks
        sgemm_k<4><<<grid, 256>>>(s2, DS_, w1, hw1, H_, C, 512, DS_,
                                  nullptr, hb1, nullptr);
    }

    // 3) h_s = h1 @ h_w2 + h_b2   (2048 x 128, K=256); A = C cols 256..511
    {
        dim3 grid(DX_ / 64, ROWS_S / 64);   // 2 x 32
        sgemm_k<2><<<grid, 256>>>(C + 256, 512, hw2, nullptr, DX_, hs, DX_, H_,
                                  hb2, nullptr, nullptr);
    }

    // 4) base = x0 @ w_x + pre_q[b] + score_b1   (1152 x 256, K=128)
    {
        dim3 grid(H_ / 64, ROWS_X / 64);    // 4 x 18
        sgemm_k<3><<<grid, 256>>>(x0, DX_, w1 + (size_t)DS_ * H_, nullptr, H_,
                                  base, H_, DX_, b1, nullptr, preq);
    }

    // 5) fused logits + softmax + aggregation + output
    att_k<<<ROWS_X, 256>>>(C, base, hs, w2, b2, x0, out);
}

// round 2
// speedup vs baseline: 1.5434x; 1.5434x over previous
#include <cuda_runtime.h>
#include <math.h>

#define B_  32
#define M_  64
#define Kk_ 36
#define DS_ 512
#define DX_ 128
#define DQ_ 512
#define H_  256
#define ROWS_S 2048
#define ROWS_X 1152

// Scratch (allocation-free rule: __device__ globals)
__device__ __align__(16) float g_preq[B_*H_];        // 32*256
__device__ __align__(16) float g_C[ROWS_S*512];      // [2048,512]: cols 0:256 pre_s, 256:512 h1=relu(s2@hw1+b)
__device__ __align__(16) float g_hs[ROWS_S*DX_];     // 2048*128
__device__ __align__(16) float g_base[ROWS_X*H_];    // 1152*256

// Packed dual-FMA (sm_103a): d = a*b + d elementwise on float2
__device__ __forceinline__ void fma2(float2 &d, const float2 &a, const float2 &b) {
    asm("fma.rn.f32x2 %0, %1, %2, %0;"
        : "+l"(reinterpret_cast<unsigned long long&>(d))
        : "l"(reinterpret_cast<const unsigned long long&>(a)),
          "l"(reinterpret_cast<const unsigned long long&>(b)));
}

// ---------------------------------------------------------------------------
// L1: bid<128 : C[2048,512] = [ s2@w_s | relu(s2@hw1+hb1) ]
//     128x64 tile, BK=16, 256 thr, 8x4 microtile (4 m-pairs x 4 n), dbl-buffered
//     bid>=128: preq[b] = q[b] @ w_q   (32 blocks filling idle SMs)
// ---------------------------------------------------------------------------
__global__ void __launch_bounds__(256) k1(
    const float* __restrict__ s2, const float* __restrict__ w1,
    const float* __restrict__ hw1, const float* __restrict__ hb1,
    const float* __restrict__ q, float* __restrict__ C,
    float* __restrict__ preq)
{
    __shared__ float As[2][16][132];
    __shared__ float Bs[2][16][64];
    const int tid = threadIdx.x;
    const int bx  = blockIdx.x;

    if (bx >= 128) {  // ---- pre_q blocks ----
        float* qs = &As[0][0][0];
        const int b = bx - 128;
        for (int d = tid; d < DQ_; d += 256) qs[d] = q[b*DQ_ + d];
        __syncthreads();
        const float* wq = w1 + (size_t)(DS_ + DX_) * H_;
        float a0=0.f, a1=0.f, a2=0.f, a3=0.f;
        #pragma unroll 4
        for (int d = 0; d < DQ_; d += 4) {
            a0 = fmaf(qs[d+0], wq[(size_t)(d+0)*H_ + tid], a0);
            a1 = fmaf(qs[d+1], wq[(size_t)(d+1)*H_ + tid], a1);
            a2 = fmaf(qs[d+2], wq[(size_t)(d+2)*H_ + tid], a2);
            a3 = fmaf(qs[d+3], wq[(size_t)(d+3)*H_ + tid], a3);
        }
        preq[b*H_ + tid] = (a0+a1)+(a2+a3);
        return;
    }

    const int bn = bx & 7, bm = bx >> 3;
    const int m0 = bm * 128, n0 = bn * 64;
    const float* Bp; const float* bias = hb1; bool relu; int bcol;
    if (n0 < 256) { Bp = w1;  bcol = n0;       relu = false; }
    else          { Bp = hw1; bcol = n0 - 256; relu = true;  }

    const int tx = tid & 15, ty = tid >> 4;
    const int ar = tid >> 2;             // 0..63
    const int ac = (tid & 3) << 2;       // 0,4,8,12
    const int bkr = tid >> 4;            // 0..15
    const int bn4 = (tid & 15) << 2;     // 0..60

    const float* Ag  = s2 + (size_t)(m0 + ar) * DS_ + ac;
    const float* Ag2 = Ag + (size_t)64 * DS_;
    const float* Bg  = Bp + (size_t)bkr * H_ + bcol + bn4;

    float2 acc[4][4];
    #pragma unroll
    for (int i = 0; i < 4; i++)
        #pragma unroll
        for (int j = 0; j < 4; j++) acc[i][j] = make_float2(0.f, 0.f);

    float4 av0 = *reinterpret_cast<const float4*>(Ag);
    float4 av1 = *reinterpret_cast<const float4*>(Ag2);
    float4 bv  = *reinterpret_cast<const float4*>(Bg);
    As[0][ac+0][ar] = av0.x; As[0][ac+1][ar] = av0.y;
    As[0][ac+2][ar] = av0.z; As[0][ac+3][ar] = av0.w;
    As[0][ac+0][ar+64] = av1.x; As[0][ac+1][ar+64] = av1.y;
    As[0][ac+2][ar+64] = av1.z; As[0][ac+3][ar+64] = av1.w;
    *reinterpret_cast<float4*>(&Bs[0][bkr][bn4]) = bv;
    __syncthreads();

    #pragma unroll 1
    for (int kt = 0; kt < 32; kt++) {
        const int buf = kt & 1;
        if (kt < 31) {
            av0 = *reinterpret_cast<const float4*>(Ag  + (kt+1)*16);
            av1 = *reinterpret_cast<const float4*>(Ag2 + (kt+1)*16);
            bv  = *reinterpret_cast<const float4*>(Bg  + (size_t)(kt+1)*16*H_);
        }
        #pragma unroll
        for (int kk = 0; kk < 16; kk++) {
            float4 al = *reinterpret_cast<const float4*>(&As[buf][kk][ty*8]);
            float4 ah = *reinterpret_cast<const float4*>(&As[buf][kk][ty*8+4]);
            float4 b4 = *reinterpret_cast<const float4*>(&Bs[buf][kk][tx*4]);
            float2 a2v[4] = {{al.x,al.y},{al.z,al.w},{ah.x,ah.y},{ah.z,ah.w}};
            float2 bd[4]  = {{b4.x,b4.x},{b4.y,b4.y},{b4.z,b4.z},{b4.w,b4.w}};
            #pragma unroll
            for (int i = 0; i < 4; i++)
                #pragma unroll
                for (int j = 0; j < 4; j++)
                    fma2(acc[i][j], a2v[i], bd[j]);
        }
        if (kt < 31) {
            const int nb = buf ^ 1;
            As[nb][ac+0][ar] = av0.x; As[nb][ac+1][ar] = av0.y;
            As[nb][ac+2][ar] = av0.z; As[nb][ac+3][ar] = av0.w;
            As[nb][ac+0][ar+64] = av1.x; As[nb][ac+1][ar+64] = av1.y;
            As[nb][ac+2][ar+64] = av1.z; As[nb][ac+3][ar+64] = av1.w;
            *reinterpret_cast<float4*>(&Bs[nb][bkr][bn4]) = bv;
        }
        __syncthreads();
    }

    float4 b4 = make_float4(0.f,0.f,0.f,0.f);
    if (relu) b4 = *reinterpret_cast<const float4*>(&bias[bcol + tx*4]);
    float* Cr = C + (size_t)(m0 + ty*8) * 512 + n0 + tx*4;
    #pragma unroll
    for (int i = 0; i < 4; i++) {
        float4 lo = make_float4(acc[i][0].x, acc[i][1].x, acc[i][2].x, acc[i][3].x);
        float4 hi = make_float4(acc[i][0].y, acc[i][1].y, acc[i][2].y, acc[i][3].y);
        if (relu) {
            lo.x = fmaxf(lo.x + b4.x, 0.f); lo.y = fmaxf(lo.y + b4.y, 0.f);
            lo.z = fmaxf(lo.z + b4.z, 0.f); lo.w = fmaxf(lo.w + b4.w, 0.f);
            hi.x = fmaxf(hi.x + b4.x, 0.f); hi.y = fmaxf(hi.y + b4.y, 0.f);
            hi.z = fmaxf(hi.z + b4.z, 0.f); hi.w = fmaxf(hi.w + b4.w, 0.f);
        }
        *reinterpret_cast<float4*>(Cr + (size_t)(2*i  )*512) = lo;
        *reinterpret_cast<float4*>(Cr + (size_t)(2*i+1)*512) = hi;
    }
}

// ---------------------------------------------------------------------------
// L2: bid<64 : hs[2048,128] = h1 @ hw2 + hb2      (64x64 tiles, K=256)
//     bid>=64: base[1152,256] = x0@w_x + preq[row/36] + b1  (64x64, K=128)
//     256 thr, 4x4 micro (2 m-pairs x 4 n), double-buffered.
// ---------------------------------------------------------------------------
__global__ void __launch_bounds__(256) k2(
    const float* __restrict__ C, const float* __restrict__ hw2,
    const float* __restrict__ hb2, const float* __restrict__ x0,
    const float* __restrict__ w1, const float* __restrict__ b1,
    const float* __restrict__ preq,
    float* __restrict__ hs, float* __restrict__ base)
{
    __shared__ float As[2][16][68];
    __shared__ float Bs[2][16][64];
    const int tid = threadIdx.x;
    const int bx  = blockIdx.x;

    const float* A; const float* Bp; int lda, ldb, nt, m0, n0, mode;
    if (bx < 64) {          // hs tiles: 32 x 2
        mode = 0; const int tm = bx >> 1, tn = bx & 1;
        m0 = tm*64; n0 = tn*64;
        A = C + 256; lda = 512; Bp = hw2; ldb = 128; nt = 256/16;
    } else {                // base tiles: 18 x 4
        mode = 1; const int bb = bx - 64; const int tm = bb >> 2, tn = bb & 3;
        m0 = tm*64; n0 = tn*64;
        A = x0; lda = 128; Bp = w1 + (size_t)DS_*H_; ldb = 256; nt = 128/16;
    }

    const int tx = tid & 15, ty = tid >> 4;
    const int ar = tid >> 2;
    const int ac = (tid & 3) << 2;
    const int bkr = tid >> 4;
    const int bn4 = (tid & 15) << 2;

    const float* Ag = A  + (size_t)(m0 + ar) * lda + ac;
    const float* Bg = Bp + (size_t)bkr * ldb + n0 + bn4;

    float2 acc[2][4];
    #pragma unroll
    for (int i = 0; i < 2; i++)
        #pragma unroll
        for (int j = 0; j < 4; j++) acc[i][j] = make_float2(0.f, 0.f);

    float4 av = *reinterpret_cast<const float4*>(Ag);
    float4 bv = *reinterpret_cast<const float4*>(Bg);
    As[0][ac+0][ar] = av.x; As[0][ac+1][ar] = av.y;
    As[0][ac+2][ar] = av.z; As[0][ac+3][ar] = av.w;
    *reinterpret_cast<float4*>(&Bs[0][bkr][bn4]) = bv;
    __syncthreads();

    #pragma unroll 1
    for (int kt = 0; kt < nt; kt++) {
        const int buf = kt & 1;
        if (kt + 1 < nt) {
            av = *reinterpret_cast<const float4*>(Ag + (kt+1)*16);
            bv = *reinterpret_cast<const float4*>(Bg + (size_t)(kt+1)*16*ldb);
        }
        #pragma unroll
        for (int kk = 0; kk < 16; kk++) {
            float4 a4 = *reinterpret_cast<const float4*>(&As[buf][kk][ty*4]);
            float4 b4 = *reinterpret_cast<const float4*>(&Bs[buf][kk][tx*4]);
            float2 a2v[2] = {{a4.x,a4.y},{a4.z,a4.w}};
            float2 bd[4]  = {{b4.x,b4.x},{b4.y,b4.y},{b4.z,b4.z},{b4.w,b4.w}};
            #pragma unroll
            for (int i = 0; i < 2; i++)
                #pragma unroll
                for (int j = 0; j < 4; j++)
                    fma2(acc[i][j], a2v[i], bd[j]);
        }
        if (kt + 1 < nt) {
            const int nb = buf ^ 1;
            As[nb][ac+0][ar] = av.x; As[nb][ac+1][ar] = av.y;
            As[nb][ac+2][ar] = av.z; As[nb][ac+3][ar] = av.w;
            *reinterpret_cast<float4*>(&Bs[nb][bkr][bn4]) = bv;
        }
        __syncthreads();
    }

    if (mode == 0) {
        float4 bb = *reinterpret_cast<const float4*>(&hb2[n0 + tx*4]);
        float* Or = hs + (size_t)(m0 + ty*4) * DX_ + n0 + tx*4;
        #pragma unroll
        for (int i = 0; i < 2; i++) {
            float4 lo = make_float4(acc[i][0].x+bb.x, acc[i][1].x+bb.y, acc[i][2].x+bb.z, acc[i][3].x+bb.w);
            float4 hi = make_float4(acc[i][0].y+bb.x, acc[i][1].y+bb.y, acc[i][2].y+bb.z, acc[i][3].y+bb.w);
            *reinterpret_cast<float4*>(Or + (size_t)(2*i  )*DX_) = lo;
            *reinterpret_cast<float4*>(Or + (size_t)(2*i+1)*DX_) = hi;
        }
    } else {
        float4 bb = *reinterpret_cast<const float4*>(&b1[n0 + tx*4]);
        #pragma unroll
        for (int i = 0; i < 2; i++) {
            const int r0 = m0 + ty*4 + 2*i;
            float4 p0 = *reinterpret_cast<const float4*>(&preq[(r0   /Kk_)*H_ + n0 + tx*4]);
            float4 p1 = *reinterpret_cast<const float4*>(&preq[((r0+1)/Kk_)*H_ + n0 + tx*4]);
            float4 lo = make_float4(acc[i][0].x+bb.x+p0.x, acc[i][1].x+bb.y+p0.y,
                                    acc[i][2].x+bb.z+p0.z, acc[i][3].x+bb.w+p0.w);
            float4 hi = make_float4(acc[i][0].y+bb.x+p1.x, acc[i][1].y+bb.y+p1.y,
                                    acc[i][2].y+bb.z+p1.z, acc[i][3].y+bb.w+p1.w);
            *reinterpret_cast<float4*>(&base[(size_t)(r0  )*H_ + n0 + tx*4]) = lo;
            *reinterpret_cast<float4*>(&base[(size_t)(r0+1)*H_ + n0 + tx*4]) = hi;
        }
    }
}

// ---------------------------------------------------------------------------
// L3: fused logits + softmax + aggregation + x0 copy. 4 k per block.
//     grid = 32 b * 9 kgroups = 288 blocks, 256 threads.
//     (score_b2 omitted: constant shift cancels in softmax.)
// ---------------------------------------------------------------------------
__global__ void __launch_bounds__(256) att_k(
    const float* __restrict__ Cmat,   // [2048,512] (pre_s cols 0..255)
    const float* __restrict__ base,   // [1152,256]
    const float* __restrict__ hsm,    // [2048,128]
    const float* __restrict__ w2,     // [256]
    const float* __restrict__ x0,     // [1152,128]
    float* __restrict__ out)          // [1152,256]
{
    const int b  = blockIdx.x / 9;
    const int kg = blockIdx.x % 9;
    const int bk0 = b * Kk_ + kg * 4;
    const int tid = threadIdx.x;
    const int warp = tid >> 5, lane = tid & 31;

    __shared__ float base_s[4][H_];
    __shared__ float w2s[H_];
    __shared__ float lgt[4][M_];
    __shared__ float ew[4][M_];
    __shared__ float sinv[4];

    for (int idx = tid; idx < 4*H_; idx += 256) {
        base_s[idx >> 8][idx & 255] = base[(size_t)(bk0 + (idx >> 8)) * H_ + (idx & 255)];
    }
    w2s[tid] = w2[tid];
    __syncthreads();

    // logits: warp w handles m = w*8 .. w*8+7; pre_s row reused across 4 ks
    const float* pres = Cmat + (size_t)(b * M_) * 512;
    #pragma unroll
    for (int mi = 0; mi < 8; mi++) {
        const int m = warp * 8 + mi;
        const float* row = pres + (size_t)m * 512;
        float r[8];
        #pragma unroll
        for (int j = 0; j < 8; j++) r[j] = row[lane + 32*j];
        #pragma unroll
        for (int k = 0; k < 4; k++) {
            float acc = 0.f;
            #pragma unroll
            for (int j = 0; j < 8; j++) {
                const int h = lane + 32*j;
                acc = fmaf(fmaxf(r[j] + base_s[k][h], 0.f), w2s[h], acc);
            }
            #pragma unroll
            for (int off = 16; off; off >>= 1)
                acc += __shfl_xor_sync(0xffffffffu, acc, off);
            if (lane == 0) lgt[k][m] = acc;
        }
    }
    __syncthreads();

    // softmax over m: warps 0..3, one k each
    if (warp < 4) {
        const int k = warp;
        float l0 = lgt[k][lane], l1 = lgt[k][lane + 32];
        float mx = fmaxf(l0, l1);
        #pragma unroll
        for (int off = 16; off; off >>= 1)
            mx = fmaxf(mx, __shfl_xor_sync(0xffffffffu, mx, off));
        float e0 = expf(l0 - mx), e1 = expf(l1 - mx);
        float s = e0 + e1;
        #pragma unroll
        for (int off = 16; off; off >>= 1)
            s += __shfl_xor_sync(0xffffffffu, s, off);
        ew[k][lane] = e0; ew[k][lane + 32] = e1;
        if (lane == 0) sinv[k] = 1.f / s;
    }
    __syncthreads();

    // aggregation: thread = (kpair, f); hs column read shared by 2 ks
    {
        const int f  = tid & 127;
        const int kp = tid >> 7;          // 0 or 1
        const int k0 = kp * 2, k1 = k0 + 1;
        const float* hb = hsm + (size_t)(b * M_) * DX_ + f;
        float a0 = 0.f, a1 = 0.f;
        #pragma unroll 8
        for (int m = 0; m < M_; m++) {
            const float v = hb[(size_t)m * DX_];
            a0 = fmaf(ew[k0][m], v, a0);
            a1 = fmaf(ew[k1][m], v, a1);
        }
        out[(size_t)(bk0 + k0) * 256 + 128 + f] = a0 * sinv[k0];
        out[(size_t)(bk0 + k1) * 256 + 128 + f] = a1 * sinv[k1];
    }
    // x0 copy
    for (int idx = tid; idx < 4 * DX_; idx += 256) {
        const int k = idx >> 7, f = idx & 127;
        out[(size_t)(bk0 + k) * 256 + f] = x0[(size_t)(bk0 + k) * DX_ + f];
    }
}

// ---------------------------------------------------------------------------
extern "C" void kernel_launch(void* const* d_in, const int* in_sizes, int n_in,
                              void* d_out, int out_size)
{
    (void)in_sizes; (void)n_in; (void)out_size;
    const float* s2  = (const float*)d_in[0];
    const float* x0  = (const float*)d_in[1];
    const float* q   = (const float*)d_in[2];
    const float* w1  = (const float*)d_in[3];
    const float* b1  = (const float*)d_in[4];
    const float* w2  = (const float*)d_in[5];
    /* b2 unused: cancels in softmax */
    const float* hw1 = (const float*)d_in[7];
    const float* hb1 = (const float*)d_in[8];
    const float* hw2 = (const float*)d_in[9];
    const float* hb2 = (const float*)d_in[10];
    float* out = (float*)d_out;

    float *preq, *C, *hs, *base;
    cudaGetSymbolAddress((void**)&preq, g_preq);
    cudaGetSymbolAddress((void**)&C,    g_C);
    cudaGetSymbolAddress((void**)&hs,   g_hs);
    cudaGetSymbolAddress((void**)&base, g_base);

    // L1: big GEMM (128 tiles) + preq (32 blocks)
    k1<<<160, 256>>>(s2, w1, hw1, hb1, q, C, preq);
    // L2: hs (64 tiles) + base (72 tiles)
    k2<<<136, 256>>>(C, hw2, hb2, x0, w1, b1, preq, hs, base);
    // L3: fused attention + output
    att_k<<<288, 256>>>(C, base, hs, w2, x0, out);
}